// round 5
// baseline (speedup 1.0000x reference)
#include <cuda_runtime.h>

#define BM 128
#define BN 128
#define BK 32
#define BKS 36          // padded smem stride (conflict-free)
#define NT_ 256

// ---------------- scratch (static device globals; no runtime allocation) ----
__device__ float g_E0[8192 * 1024];   // e_gen0
__device__ float g_E1[8192 * 512];    // e_gen1
__device__ float g_D2[8192 * 512];    // e_disc2
__device__ float g_D3[8192 * 256];    // e_disc3
__device__ float g_S1[8192 * 512];    // e_gen1 + e_disc1
__device__ float g_S2[8192 * 512];    // e_gen2 + e_disc2

__device__ __forceinline__ float* scratch_ptr(int id) {
    switch (id) {
        case 0:  return g_E0;
        case 1:  return g_E1;
        case 2:  return g_D2;
        case 3:  return g_D3;
        case 4:  return g_S1;
        default: return g_S2;
    }
}

struct GArgs {
    const float* A0; int a0Id; const float* W0; int K0;
    int a1Id; const float* W1; int K1;          // K1==0 -> single GEMM (A1 always scratch)
    int N;                                      // output cols (256/512/1024)
    int mode;                                   // 0: out=base-C  1: out=other+base-C  2: LIF
    const float* base;
    int otherId;                                // mode 1: scratch id of 'other'
    float* outPtr; int outId;                   // outId>=0 -> scratch, else outPtr
    const float* jp; const float* vp; const float* xp; int sumId; // mode 2
    int colOff;                                 // mode 2: 0 or 2048
};

__device__ __forceinline__ unsigned f2tf(float f) {
    unsigned u;
    asm("cvt.rna.tf32.f32 %0, %1;" : "=r"(u) : "f"(f));
    return u;
}

__device__ __forceinline__ void mma_tf32(float c[4], const unsigned a[4], const unsigned b[2]) {
    asm volatile(
        "mma.sync.aligned.m16n8k8.row.col.f32.tf32.tf32.f32 "
        "{%0,%1,%2,%3}, {%4,%5,%6,%7}, {%8,%9}, {%0,%1,%2,%3};\n"
        : "+f"(c[0]), "+f"(c[1]), "+f"(c[2]), "+f"(c[3])
        : "r"(a[0]), "r"(a[1]), "r"(a[2]), "r"(a[3]), "r"(b[0]), "r"(b[1]));
}

// NT GEMM: C[b,n] = sum_k A[b,k] * W[n,k], optionally accumulating a second
// (A1,W1,K1) pair into the same tile, then a fused epilogue.
__global__ __launch_bounds__(NT_, 1)
void gemm_nt_fused(GArgs g) {
    __shared__ unsigned As[BM * BKS];
    __shared__ unsigned Ws[BN * BKS];

    const int tid  = threadIdx.x;
    const int bm   = blockIdx.x * BM;
    const int bn   = blockIdx.y * BN;
    const int lane = tid & 31;
    const int wid  = tid >> 5;
    const int wm   = (wid >> 2) * 64;     // warp row offset (0/64)
    const int wn   = (wid & 3) * 32;      // warp col offset (0..96)
    const int grp  = lane >> 2;
    const int tig  = lane & 3;
    const int lr   = tid >> 3;            // loader row 0..31
    const int lc   = (tid & 7) * 4;       // loader col 0..28

    const float* Aext0 = (g.a0Id >= 0) ? scratch_ptr(g.a0Id) : g.A0;
    const float* Aext1 = (g.K1 > 0)    ? scratch_ptr(g.a1Id) : nullptr;
    float*       outP  = (g.outId >= 0) ? scratch_ptr(g.outId) : g.outPtr;

    float c[4][4][4];
    #pragma unroll
    for (int i = 0; i < 4; i++)
        #pragma unroll
        for (int j = 0; j < 4; j++)
            #pragma unroll
            for (int k = 0; k < 4; k++) c[i][j][k] = 0.f;

    #pragma unroll 1
    for (int pair = 0; pair < 2; ++pair) {
        const float* A = pair ? Aext1 : Aext0;
        const float* W = pair ? g.W1 : g.W0;
        const int    K = pair ? g.K1 : g.K0;
        if (K == 0) break;

        const float* Ap = A + (size_t)(bm + lr) * K + lc;
        const float* Wp = W + (size_t)(bn + lr) * K + lc;

        float4 ra[4], rw[4];
        #pragma unroll
        for (int i = 0; i < 4; i++) {
            ra[i] = *(const float4*)(Ap + (size_t)(32 * i) * K);
            rw[i] = *(const float4*)(Wp + (size_t)(32 * i) * K);
        }

        #pragma unroll 1
        for (int kt = 0; kt < K; kt += BK) {
            #pragma unroll
            for (int i = 0; i < 4; i++) {
                unsigned* pa = &As[(lr + 32 * i) * BKS + lc];
                *(uint4*)pa = make_uint4(f2tf(ra[i].x), f2tf(ra[i].y), f2tf(ra[i].z), f2tf(ra[i].w));
                unsigned* pw = &Ws[(lr + 32 * i) * BKS + lc];
                *(uint4*)pw = make_uint4(f2tf(rw[i].x), f2tf(rw[i].y), f2tf(rw[i].z), f2tf(rw[i].w));
            }
            __syncthreads();

            if (kt + BK < K) {
                #pragma unroll
                for (int i = 0; i < 4; i++) {
                    ra[i] = *(const float4*)(Ap + (size_t)(32 * i) * K + kt + BK);
                    rw[i] = *(const float4*)(Wp + (size_t)(32 * i) * K + kt + BK);
                }
            }

            #pragma unroll
            for (int ks = 0; ks < BK; ks += 8) {
                unsigned af[4][4], bf[4][2];
                #pragma unroll
                for (int mt = 0; mt < 4; ++mt) {
                    int r0 = (wm + mt * 16 + grp) * BKS + ks + tig;
                    af[mt][0] = As[r0];
                    af[mt][1] = As[r0 + 8 * BKS];
                    af[mt][2] = As[r0 + 4];
                    af[mt][3] = As[r0 + 8 * BKS + 4];
                }
                #pragma unroll
                for (int nt = 0; nt < 4; ++nt) {
                    int n0 = (wn + nt * 8 + grp) * BKS + ks + tig;
                    bf[nt][0] = Ws[n0];
                    bf[nt][1] = Ws[n0 + 4];
                }
                #pragma unroll
                for (int mt = 0; mt < 4; ++mt)
                    #pragma unroll
                    for (int nt = 0; nt < 4; ++nt)
                        mma_tf32(c[mt][nt], af[mt], bf[nt]);
            }
            __syncthreads();
        }
    }

    // ---------------- epilogue ----------------
    if (g.mode < 2) {
        const float* other = (g.mode == 1) ? scratch_ptr(g.otherId) : nullptr;
        #pragma unroll
        for (int mt = 0; mt < 4; ++mt) {
            #pragma unroll
            for (int nt = 0; nt < 4; ++nt) {
                int row = bm + wm + mt * 16 + grp;
                int col = bn + wn + nt * 8 + tig * 2;
                #pragma unroll
                for (int h = 0; h < 2; ++h) {
                    int r = row + h * 8;
                    size_t idx = (size_t)r * g.N + col;
                    float c0 = c[mt][nt][2 * h], c1 = c[mt][nt][2 * h + 1];
                    float2 b = *(const float2*)(g.base + idx);
                    float2 o = make_float2(b.x - c0, b.y - c1);
                    if (g.mode == 1) {
                        float2 t = *(const float2*)(other + idx);
                        o.x += t.x; o.y += t.y;
                    }
                    *(float2*)(outP + idx) = o;
                }
            }
        }
    } else {
        // total = C - sum ; LIF update ; write [j|v|x|s] blocks (stride 4096)
        const float* sump = scratch_ptr(g.sumId);
        #pragma unroll
        for (int mt = 0; mt < 4; ++mt) {
            #pragma unroll
            for (int nt = 0; nt < 4; ++nt) {
                int row = bm + wm + mt * 16 + grp;
                int col = bn + wn + nt * 8 + tig * 2;
                #pragma unroll
                for (int h = 0; h < 2; ++h) {
                    int r = row + h * 8;
                    size_t sidx = (size_t)r * 512 + col;
                    float2 jj = *(const float2*)(g.jp + sidx);
                    float2 vv = *(const float2*)(g.vp + sidx);
                    float2 xx = *(const float2*)(g.xp + sidx);
                    float2 ss = *(const float2*)(sump + sidx);

                    float t0 = c[mt][nt][2 * h]     - ss.x;
                    float t1 = c[mt][nt][2 * h + 1] - ss.y;

                    float jn0 = jj.x + 0.1f * (t0 - 0.25f * jj.x);
                    float jn1 = jj.y + 0.1f * (t1 - 0.25f * jj.y);
                    float vn0 = vv.x + 0.05f * (jn0 - vv.x);
                    float vn1 = vv.y + 0.05f * (jn1 - vv.y);
                    float sp0 = vn0 > 0.4f ? 1.0f : 0.0f;
                    float sp1 = vn1 > 0.4f ? 1.0f : 0.0f;
                    vn0 *= (1.0f - sp0);
                    vn1 *= (1.0f - sp1);
                    float xn0 = xx.x - 0.05f * xx.x + sp0;
                    float xn1 = xx.y - 0.05f * xx.y + sp1;

                    float* ob = outP + (size_t)r * 4096 + g.colOff + col;
                    *(float2*)(ob)        = make_float2(jn0, jn1);
                    *(float2*)(ob + 512)  = make_float2(vn0, vn1);
                    *(float2*)(ob + 1024) = make_float2(xn0, xn1);
                    *(float2*)(ob + 1536) = make_float2(sp0, sp1);
                }
            }
        }
    }
}

static void run_gemm(const GArgs& a) {
    dim3 grid(8192 / BM, a.N / BN);
    gemm_nt_fused<<<grid, NT_>>>(a);
}

extern "C" void kernel_launch(void* const* d_in, const int* in_sizes, int n_in,
                              void* d_out, int out_size) {
    (void)in_sizes; (void)n_in; (void)out_size;
    const float* x_input  = (const float*)d_in[0];
    const float* y_target = (const float*)d_in[1];
    const float* j1 = (const float*)d_in[2];
    const float* v1 = (const float*)d_in[3];
    const float* s1 = (const float*)d_in[4];
    const float* x1 = (const float*)d_in[5];
    const float* j2 = (const float*)d_in[6];
    const float* v2 = (const float*)d_in[7];
    const float* s2 = (const float*)d_in[8];
    const float* x2 = (const float*)d_in[9];
    const float* W0 = (const float*)d_in[10];
    const float* W1 = (const float*)d_in[11];
    const float* W2 = (const float*)d_in[12];
    const float* V0 = (const float*)d_in[13];
    const float* V1 = (const float*)d_in[14];
    const float* V2 = (const float*)d_in[15];
    const float* Eg0 = (const float*)d_in[16];
    const float* Eg1 = (const float*)d_in[17];
    // d_in[18] (Eg2) and d_in[19] (Ed0) are unused by the reference math
    const float* Ed1 = (const float*)d_in[20];
    const float* Ed2 = (const float*)d_in[21];
    float* out = (float*)d_out;

    // scratch ids: 0=E0(e_gen0) 1=E1(e_gen1) 2=D2(e_disc2) 3=D3(e_disc3) 4=S1 5=S2

    // --- stage 1: error neurons ---
    // e_gen0 = x_input - s1 @ W0^T               -> E0
    run_gemm(GArgs{s1, -1, W0, 512,  -1, nullptr, 0, 1024, 0,
                   x_input, -1, nullptr, 0, nullptr, nullptr, nullptr, -1, 0});
    // e_gen1 = x1 - s2 @ W1^T                    -> E1
    run_gemm(GArgs{s2, -1, W1, 512,  -1, nullptr, 0, 512, 0,
                   x1, -1, nullptr, 1, nullptr, nullptr, nullptr, -1, 0});
    // Sum1 = e_gen1 + (x1 - x_input @ V0^T)      -> S1
    run_gemm(GArgs{x_input, -1, V0, 1024,  -1, nullptr, 0, 512, 1,
                   x1, 1, nullptr, 4, nullptr, nullptr, nullptr, -1, 0});
    // e_disc2 = x2 - s1 @ V1^T                   -> D2
    run_gemm(GArgs{s1, -1, V1, 512,  -1, nullptr, 0, 512, 0,
                   x2, -1, nullptr, 2, nullptr, nullptr, nullptr, -1, 0});
    // Sum2 = e_disc2 + (x2 - y_target @ W2^T)    -> S2
    run_gemm(GArgs{y_target, -1, W2, 256,  -1, nullptr, 0, 512, 1,
                   x2, 2, nullptr, 5, nullptr, nullptr, nullptr, -1, 0});
    // e_disc3 = y_target - s2 @ V2^T             -> D3
    run_gemm(GArgs{s2, -1, V2, 512,  -1, nullptr, 0, 256, 0,
                   y_target, -1, nullptr, 3, nullptr, nullptr, nullptr, -1, 0});

    // --- stage 2: total input + LIF, fused, writes d_out directly ---
    // total1 = E0@Eg0^T + D2@Ed1^T - S1 ; LIF -> cols [0,2048)
    run_gemm(GArgs{nullptr, 0, Eg0, 1024,  2, Ed1, 512, 512, 2,
                   nullptr, -1, out, -1, j1, v1, x1, 4, 0});
    // total2 = E1@Eg1^T + D3@Ed2^T - S2 ; LIF -> cols [2048,4096)
    run_gemm(GArgs{nullptr, 1, Eg1, 512,  3, Ed2, 256, 512, 2,
                   nullptr, -1, out, -1, j2, v2, x2, 5, 2048});
}

// round 7
// speedup vs baseline: 1.5410x; 1.5410x over previous
#include <cuda_runtime.h>

#define BKS 36           // padded smem row stride in words (conflict-free)
#define ABUF (128 * BKS) // one 128-row tile buffer, in words

// ---------------- scratch (static device globals; no runtime allocation) ----
__device__ float g_E0[8192 * 1024];   // e_gen0
__device__ float g_E1[8192 * 512];    // e_gen1
__device__ float g_D1[8192 * 512];    // e_disc1
__device__ float g_D2[8192 * 512];    // e_disc2
__device__ float g_G2[8192 * 512];    // e_gen2
__device__ float g_D3[8192 * 256];    // e_disc3

__device__ __forceinline__ float* scratch_ptr(int id) {
    switch (id) {
        case 0:  return g_E0;
        case 1:  return g_E1;
        case 2:  return g_D1;
        case 3:  return g_D2;
        case 4:  return g_G2;
        default: return g_D3;
    }
}

struct Job {
    const float* A0; int a0Id; const float* W0; int K0;
    int a1Id; const float* W1; int K1;   // K1==0 -> single GEMM (A1 always scratch)
    int N;                               // output cols (256/512/1024)
    int mode;                            // 0: out = base - C   2: LIF(total = C - sub1 - sub2)
    const float* base;                   // mode 0
    int sub1Id, sub2Id;                  // mode 2
    float* outPtr; int outId;            // outId>=0 -> scratch, else outPtr
    const float* jp; const float* vp; const float* xp;  // mode 2
    int colOff;                          // mode 2: 0 or 2048
    int blockStart;                      // flat-bid start (non-interleaved dispatch)
};

struct Params {
    Job jobs[6];
    int nJobs;
    int interleave;                      // 1: job = bid&1, local = bid>>1
};

__device__ __forceinline__ unsigned f2tf(float f) {
    unsigned u;
    asm("cvt.rna.tf32.f32 %0, %1;" : "=r"(u) : "f"(f));
    return u;
}

__device__ __forceinline__ void mma_tf32(float c[4], const unsigned a[4], const unsigned b[2]) {
    asm volatile(
        "mma.sync.aligned.m16n8k8.row.col.f32.tf32.tf32.f32 "
        "{%0,%1,%2,%3}, {%4,%5,%6,%7}, {%8,%9}, {%0,%1,%2,%3};\n"
        : "+f"(c[0]), "+f"(c[1]), "+f"(c[2]), "+f"(c[3])
        : "r"(a[0]), "r"(a[1]), "r"(a[2]), "r"(a[3]), "r"(b[0]), "r"(b[1]));
}

// NT GEMM: C[b,n] = sum_k A[b,k] * W[n,k], optional second (A1,W1,K1) accumulated
// into the same tile, fused epilogue. 128x128x32 tiles, double-buffered smem,
// one __syncthreads per k-slab, 2 CTAs/SM.
__global__ __launch_bounds__(256, 2)
void snn_gemm(Params p) {
    extern __shared__ unsigned smem[];
    unsigned* As = smem;               // [2][ABUF]
    unsigned* Ws = smem + 2 * ABUF;    // [2][ABUF]

    // ---- job dispatch ----
    int bid = blockIdx.x;
    int jidx, local;
    if (p.interleave) {
        jidx  = bid & 1;
        local = bid >> 1;
    } else {
        jidx = 0;
        while (jidx + 1 < p.nJobs && bid >= p.jobs[jidx + 1].blockStart) ++jidx;
        local = bid - p.jobs[jidx].blockStart;
    }
    const Job g = p.jobs[jidx];
    const int bm = (local & 63) * 128;   // mBlocks = 64 always (8192/128)
    const int bn = (local >> 6) * 128;

    const float* pA0 = (g.a0Id >= 0) ? scratch_ptr(g.a0Id) : g.A0;
    const float* pA1 = (g.K1 > 0)    ? scratch_ptr(g.a1Id) : nullptr;

    const int tid  = threadIdx.x;
    const int lane = tid & 31;
    const int wid  = tid >> 5;
    const int wm   = (wid >> 2) * 64;     // warp row offset (0/64)
    const int wn   = (wid & 3) * 32;      // warp col offset (0..96)
    const int grp  = lane >> 2;
    const int tig  = lane & 3;
    const int lr   = tid >> 3;            // loader row 0..31
    const int lc   = (tid & 7) * 4;       // loader col 0..28

    float c[4][4][4];
    #pragma unroll
    for (int i = 0; i < 4; i++)
        #pragma unroll
        for (int j = 0; j < 4; j++)
            #pragma unroll
            for (int k = 0; k < 4; k++) c[i][j][k] = 0.f;

    const int ns0 = g.K0 >> 5;
    const int ns1 = g.K1 >> 5;
    const int ns  = ns0 + ns1;

    float4 ra[4], rw[4];

    // LDG slab s into ra/rw
    auto ldg_slab = [&](int s) {
        const float* A; const float* W; int K, kt;
        if (s < ns0) { A = pA0; W = g.W0; K = g.K0; kt = s << 5; }
        else         { A = pA1; W = g.W1; K = g.K1; kt = (s - ns0) << 5; }
        int offA = (bm + lr) * K + kt + lc;
        int offW = (bn + lr) * K + kt + lc;
        #pragma unroll
        for (int i = 0; i < 4; i++) {
            ra[i] = *(const float4*)(A + offA + 32 * i * K);
            rw[i] = *(const float4*)(W + offW + 32 * i * K);
        }
    };

    // cvt + STS into buffer b
    auto sts_slab = [&](int b) {
        unsigned* Ad = As + b * ABUF + lr * BKS + lc;
        unsigned* Wd = Ws + b * ABUF + lr * BKS + lc;
        #pragma unroll
        for (int i = 0; i < 4; i++) {
            *(uint4*)(Ad + 32 * i * BKS) =
                make_uint4(f2tf(ra[i].x), f2tf(ra[i].y), f2tf(ra[i].z), f2tf(ra[i].w));
            *(uint4*)(Wd + 32 * i * BKS) =
                make_uint4(f2tf(rw[i].x), f2tf(rw[i].y), f2tf(rw[i].z), f2tf(rw[i].w));
        }
    };

    // prologue: slab 0 -> buf 0
    ldg_slab(0);
    sts_slab(0);

    #pragma unroll 1
    for (int s = 0; s < ns; ++s) {
        const bool has_next = (s + 1 < ns);
        if (has_next) ldg_slab(s + 1);

        __syncthreads();   // STS(buf s&1) done by all; prior compute of buf (s+1)&1 done

        const unsigned* Ab = As + (s & 1) * ABUF;
        const unsigned* Wb = Ws + (s & 1) * ABUF;

        #pragma unroll
        for (int ks = 0; ks < 32; ks += 8) {
            unsigned bf[4][2];
            #pragma unroll
            for (int nt = 0; nt < 4; ++nt) {
                int n0 = (wn + nt * 8 + grp) * BKS + ks + tig;
                bf[nt][0] = Wb[n0];
                bf[nt][1] = Wb[n0 + 4];
            }
            #pragma unroll
            for (int mt = 0; mt < 4; ++mt) {
                int r0 = (wm + mt * 16 + grp) * BKS + ks + tig;
                unsigned af[4];
                af[0] = Ab[r0];
                af[1] = Ab[r0 + 8 * BKS];
                af[2] = Ab[r0 + 4];
                af[3] = Ab[r0 + 8 * BKS + 4];
                #pragma unroll
                for (int nt = 0; nt < 4; ++nt)
                    mma_tf32(c[mt][nt], af, bf[nt]);
            }
        }

        if (has_next) sts_slab((s + 1) & 1);
    }

    // ---------------- epilogue ----------------
    if (g.mode == 0) {
        float* outP = (g.outId >= 0) ? scratch_ptr(g.outId) : g.outPtr;
        #pragma unroll
        for (int mt = 0; mt < 4; ++mt) {
            #pragma unroll
            for (int nt = 0; nt < 4; ++nt) {
                int row = bm + wm + mt * 16 + grp;
                int col = bn + wn + nt * 8 + tig * 2;
                #pragma unroll
                for (int h = 0; h < 2; ++h) {
                    int r = row + h * 8;
                    size_t idx = (size_t)r * g.N + col;
                    float2 b = *(const float2*)(g.base + idx);
                    *(float2*)(outP + idx) =
                        make_float2(b.x - c[mt][nt][2 * h], b.y - c[mt][nt][2 * h + 1]);
                }
            }
        }
    } else {
        // total = C - sub1 - sub2 ; LIF ; write [j|v|x|s] blocks (row stride 4096)
        const float* sub1 = scratch_ptr(g.sub1Id);
        const float* sub2 = scratch_ptr(g.sub2Id);
        float* outP = g.outPtr;
        #pragma unroll
        for (int mt = 0; mt < 4; ++mt) {
            #pragma unroll
            for (int nt = 0; nt < 4; ++nt) {
                int row = bm + wm + mt * 16 + grp;
                int col = bn + wn + nt * 8 + tig * 2;
                #pragma unroll
                for (int h = 0; h < 2; ++h) {
                    int r = row + h * 8;
                    size_t sidx = (size_t)r * 512 + col;
                    float2 u1 = *(const float2*)(sub1 + sidx);
                    float2 u2 = *(const float2*)(sub2 + sidx);
                    float2 jj = *(const float2*)(g.jp + sidx);
                    float2 vv = *(const float2*)(g.vp + sidx);
                    float2 xx = *(const float2*)(g.xp + sidx);

                    float t0 = c[mt][nt][2 * h]     - u1.x - u2.x;
                    float t1 = c[mt][nt][2 * h + 1] - u1.y - u2.y;

                    float jn0 = jj.x + 0.1f * (t0 - 0.25f * jj.x);
                    float jn1 = jj.y + 0.1f * (t1 - 0.25f * jj.y);
                    float vn0 = vv.x + 0.05f * (jn0 - vv.x);
                    float vn1 = vv.y + 0.05f * (jn1 - vv.y);
                    float sp0 = vn0 > 0.4f ? 1.0f : 0.0f;
                    float sp1 = vn1 > 0.4f ? 1.0f : 0.0f;
                    vn0 *= (1.0f - sp0);
                    vn1 *= (1.0f - sp1);
                    float xn0 = xx.x - 0.05f * xx.x + sp0;
                    float xn1 = xx.y - 0.05f * xx.y + sp1;

                    float* ob = outP + (size_t)r * 4096 + g.colOff + col;
                    *(float2*)(ob)        = make_float2(jn0, jn1);
                    *(float2*)(ob + 512)  = make_float2(vn0, vn1);
                    *(float2*)(ob + 1024) = make_float2(xn0, xn1);
                    *(float2*)(ob + 1536) = make_float2(sp0, sp1);
                }
            }
        }
    }
}

#define SMEM_BYTES (4 * ABUF * 4)   // 2 buffers x (A+W) x ABUF words x 4B = 73728

extern "C" void kernel_launch(void* const* d_in, const int* in_sizes, int n_in,
                              void* d_out, int out_size) {
    (void)in_sizes; (void)n_in; (void)out_size;
    const float* x_input  = (const float*)d_in[0];
    const float* y_target = (const float*)d_in[1];
    const float* j1 = (const float*)d_in[2];
    const float* v1 = (const float*)d_in[3];
    const float* s1 = (const float*)d_in[4];
    const float* x1 = (const float*)d_in[5];
    const float* j2 = (const float*)d_in[6];
    const float* v2 = (const float*)d_in[7];
    const float* s2 = (const float*)d_in[8];
    const float* x2 = (const float*)d_in[9];
    const float* W0 = (const float*)d_in[10];
    const float* W1 = (const float*)d_in[11];
    const float* W2 = (const float*)d_in[12];
    const float* V0 = (const float*)d_in[13];
    const float* V1 = (const float*)d_in[14];
    const float* V2 = (const float*)d_in[15];
    const float* Eg0 = (const float*)d_in[16];
    const float* Eg1 = (const float*)d_in[17];
    // d_in[18] (Eg2) and d_in[19] (Ed0) are unused by the reference math
    const float* Ed1 = (const float*)d_in[20];
    const float* Ed2 = (const float*)d_in[21];
    float* out = (float*)d_out;

    cudaFuncSetAttribute(snn_gemm, cudaFuncAttributeMaxDynamicSharedMemorySize, SMEM_BYTES);

    // scratch ids: 0=E0(e_gen0) 1=E1(e_gen1) 2=D1(e_disc1) 3=D2(e_disc2) 4=G2(e_gen2) 5=D3(e_disc3)

    // ---- stage 1: six independent error-neuron GEMMs, one launch ----
    Params p1{};
    p1.nJobs = 6; p1.interleave = 0;
    // E0 = x_input - s1@W0^T          [B,1024]
    p1.jobs[0] = Job{s1, -1, W0, 512,  -1, nullptr, 0, 1024, 0, x_input, -1, -1,
                     nullptr, 0, nullptr, nullptr, nullptr, 0, 0};
    // E1 = x1 - s2@W1^T               [B,512]
    p1.jobs[1] = Job{s2, -1, W1, 512,  -1, nullptr, 0, 512, 0, x1, -1, -1,
                     nullptr, 1, nullptr, nullptr, nullptr, 0, 512};
    // D1 = x1 - x_input@V0^T          [B,512]
    p1.jobs[2] = Job{x_input, -1, V0, 1024,  -1, nullptr, 0, 512, 0, x1, -1, -1,
                     nullptr, 2, nullptr, nullptr, nullptr, 0, 768};
    // D2 = x2 - s1@V1^T               [B,512]
    p1.jobs[3] = Job{s1, -1, V1, 512,  -1, nullptr, 0, 512, 0, x2, -1, -1,
                     nullptr, 3, nullptr, nullptr, nullptr, 0, 1024};
    // G2 = x2 - y_target@W2^T         [B,512]
    p1.jobs[4] = Job{y_target, -1, W2, 256,  -1, nullptr, 0, 512, 0, x2, -1, -1,
                     nullptr, 4, nullptr, nullptr, nullptr, 0, 1280};
    // D3 = y_target - s2@V2^T         [B,256]
    p1.jobs[5] = Job{s2, -1, V2, 512,  -1, nullptr, 0, 256, 0, y_target, -1, -1,
                     nullptr, 5, nullptr, nullptr, nullptr, 0, 1536};
    snn_gemm<<<1664, 256, SMEM_BYTES>>>(p1);

    // ---- stage 2: two dual-K GEMMs + fused LIF, one launch (interleaved) ----
    Params p2{};
    p2.nJobs = 2; p2.interleave = 1;
    // total1 = E0@Eg0^T + D2@Ed1^T - E1 - D1 ; LIF(j1,v1,x1) -> cols [0,2048)
    p2.jobs[0] = Job{nullptr, 0, Eg0, 1024,  3, Ed1, 512, 512, 2, nullptr, 1, 2,
                     out, -1, j1, v1, x1, 0, 0};
    // total2 = E1@Eg1^T + D3@Ed2^T - G2 - D2 ; LIF(j2,v2,x2) -> cols [2048,4096)
    p2.jobs[1] = Job{nullptr, 1, Eg1, 512,  5, Ed2, 256, 512, 2, nullptr, 4, 3,
                     out, -1, j2, v2, x2, 2048, 0};
    snn_gemm<<<512, 256, SMEM_BYTES>>>(p2);
}